// round 6
// baseline (speedup 1.0000x reference)
#include <cuda_runtime.h>
#include <cstdint>

// Problem shape (fixed by the reference)
#define NN    8192
#define CIN   256
#define COUT  128

// Scratch (allocation rules forbid cudaMalloc; __device__ globals are the
// sanctioned mechanism). 4 MB each.
__device__ float g_T[NN * COUT];   // features @ W
__device__ float g_S[NN * COUT];   // filt ⊙ (wavelets_inv @ T)

// ---- f32x2 packed-math helpers (Blackwell FFMA2: only reachable via PTX) ----
__device__ __forceinline__ unsigned long long f32x2_dup(float a) {
    unsigned long long r;
    asm("mov.b64 %0, {%1, %1};" : "=l"(r) : "f"(a));
    return r;
}
__device__ __forceinline__ unsigned long long f32x2_fma(unsigned long long a,
                                                        unsigned long long b,
                                                        unsigned long long c) {
    unsigned long long d;
    asm("fma.rn.f32x2 %0, %1, %2, %3;" : "=l"(d) : "l"(a), "l"(b), "l"(c));
    return d;
}
__device__ __forceinline__ void f32x2_unpack(unsigned long long v, float& lo, float& hi) {
    asm("mov.b64 {%0, %1}, %2;" : "=f"(lo), "=f"(hi) : "l"(v));
}

// ----------------------------------------------------------------------------
// SGEMM: C[M,128] = A[M,K] @ B[K,128]   (row-major everywhere)
// Optional per-row scale on the output (fuses diag(filt)).
// BM=64, BN=128 (= full N), BK=16, 256 threads, per-thread 4x8 micro-tile
// held as 16 packed f32x2 accumulators.
// Grid: M/64 blocks (1-D).
// ----------------------------------------------------------------------------
template<bool SCALE>
__global__ __launch_bounds__(256)
void gwnn_sgemm128(const float* __restrict__ A,
                   const float* __restrict__ B,
                   float* __restrict__ C,
                   int K,
                   const float* __restrict__ rowScale)
{
    constexpr int BM = 64, BN = 128, BK = 16, TM = 4, TN = 8;

    __shared__ float As[BK][BM];   // transposed A tile: As[k][m]
    __shared__ float Bs[BK][BN];

    const int tid  = threadIdx.x;
    const int trow = tid >> 4;          // 0..15  (micro-tile row group)
    const int tcol = tid & 15;          // 0..15  (micro-tile col group)
    const int blockM = blockIdx.x * BM;

    // A-tile load mapping: 64x16 = 1024 floats, one float4 per thread
    const int aRow = tid >> 2;          // 0..63
    const int aCol = (tid & 3) << 2;    // 0,4,8,12
    const float* Aptr = A + (size_t)(blockM + aRow) * K + aCol;

    // accumulators: acc[i][j] is a packed pair of output columns (2j, 2j+1)
    unsigned long long acc[TM][TN / 2];
    #pragma unroll
    for (int i = 0; i < TM; i++)
        #pragma unroll
        for (int j = 0; j < TN / 2; j++)
            acc[i][j] = 0ULL;

    for (int k0 = 0; k0 < K; k0 += BK) {
        // --- load A tile (transposed into SMEM) ---
        float4 av = *reinterpret_cast<const float4*>(Aptr + k0);
        As[aCol + 0][aRow] = av.x;
        As[aCol + 1][aRow] = av.y;
        As[aCol + 2][aRow] = av.z;
        As[aCol + 3][aRow] = av.w;

        // --- load B tile: 16x128 = 2048 floats, two float4 per thread ---
        #pragma unroll
        for (int i = 0; i < 2; i++) {
            int off  = tid * 4 + i * 1024;
            int bRow = off >> 7;        // /128
            int bCol = off & 127;
            *reinterpret_cast<float4*>(&Bs[bRow][bCol]) =
                *reinterpret_cast<const float4*>(B + (size_t)(k0 + bRow) * BN + bCol);
        }
        __syncthreads();

        // --- micro-kernel ---
        #pragma unroll
        for (int kk = 0; kk < BK; kk++) {
            float4 af = *reinterpret_cast<const float4*>(&As[kk][trow * TM]);
            // b fragments: LDS.128 lands in consecutive registers, so the
            // f32x2 pairs are already packed — no mov needed.
            ulonglong2 bq0 = *reinterpret_cast<const ulonglong2*>(&Bs[kk][tcol * TN]);
            ulonglong2 bq1 = *reinterpret_cast<const ulonglong2*>(&Bs[kk][tcol * TN + 4]);
            unsigned long long bp[4] = { bq0.x, bq0.y, bq1.x, bq1.y };
            float a_[4] = { af.x, af.y, af.z, af.w };

            #pragma unroll
            for (int i = 0; i < TM; i++) {
                unsigned long long ad = f32x2_dup(a_[i]);
                #pragma unroll
                for (int j = 0; j < TN / 2; j++)
                    acc[i][j] = f32x2_fma(ad, bp[j], acc[i][j]);
            }
        }
        __syncthreads();
    }

    // --- epilogue ---
    #pragma unroll
    for (int i = 0; i < TM; i++) {
        const int row = blockM + trow * TM + i;
        float s = 1.0f;
        if (SCALE) s = rowScale[row];

        float c[TN];
        #pragma unroll
        for (int j = 0; j < TN / 2; j++) {
            float lo, hi;
            f32x2_unpack(acc[i][j], lo, hi);
            c[2 * j]     = lo * s;
            c[2 * j + 1] = hi * s;
        }
        float4 v0 = make_float4(c[0], c[1], c[2], c[3]);
        float4 v1 = make_float4(c[4], c[5], c[6], c[7]);
        float* Crow = C + (size_t)row * BN + tcol * TN;
        *reinterpret_cast<float4*>(Crow)     = v0;
        *reinterpret_cast<float4*>(Crow + 4) = v1;
    }
}

// Kernel wrappers that reference the __device__ scratch directly (no
// cudaGetSymbolAddress needed — device code can take the address).
__global__ __launch_bounds__(256)
void gwnn_stage1(const float* __restrict__ features,
                 const float* __restrict__ weight)
{
    // delegate body is the same template logic — but we can't call a __global__
    // from a __global__; instead stage1 is launched via the template directly.
}

extern "C" void kernel_launch(void* const* d_in, const int* in_sizes, int n_in,
                              void* d_out, int out_size)
{
    const float* features     = (const float*)d_in[0];   // [8192, 256]
    const float* wavelets     = (const float*)d_in[1];   // [8192, 8192]
    const float* wavelets_inv = (const float*)d_in[2];   // [8192, 8192]
    const float* weight       = (const float*)d_in[3];   // [256, 128]
    const float* filt         = (const float*)d_in[4];   // [8192]
    float* out = (float*)d_out;                          // [8192, 128]

    float* T = nullptr;
    float* S = nullptr;
    // Device-global addresses: take them via a zero-cost device-symbol lookup
    // that is graph-capture safe (no stream ops, no allocation).
    cudaGetSymbolAddress((void**)&T, g_T);
    cudaGetSymbolAddress((void**)&S, g_S);

    dim3 block(256);
    dim3 grid(NN / 64);

    // Stage 1: T = features @ W          (K = 256)
    gwnn_sgemm128<false><<<grid, block>>>(features, weight, T, CIN, nullptr);
    // Stage 2: S = filt ⊙ (Wi @ T)       (K = 8192, filt fused)
    gwnn_sgemm128<true><<<grid, block>>>(wavelets_inv, T, S, NN, filt);
    // Stage 3: out = Wv @ S              (K = 8192)
    gwnn_sgemm128<false><<<grid, block>>>(wavelets, S, out, NN, nullptr);
}

// round 17
// speedup vs baseline: 5.1241x; 5.1241x over previous
#include <cuda_runtime.h>
#include <cuda_bf16.h>
#include <cstdint>

// Problem shape (fixed by the reference)
#define NN    8192
#define CIN   256
#define COUT  128

// ---------------------------------------------------------------------------
// Scratch (__device__ globals are the sanctioned mechanism; no cudaMalloc)
// ---------------------------------------------------------------------------
__device__ float         g_T  [NN * COUT];     // stage1 out: features @ W (fp32)
__device__ __nv_bfloat16 g_Bhi[COUT * NN];     // T transposed, bf16 hi  [128][8192]
__device__ __nv_bfloat16 g_Blo[COUT * NN];     // T transposed, bf16 lo
__device__ __nv_bfloat16 g_Shi[COUT * NN];     // filt ⊙ (Wi@T) transposed, hi
__device__ __nv_bfloat16 g_Slo[COUT * NN];     // ... lo

// ===========================================================================
// Helpers (base sm_103 target only: mma.sync / ldmatrix / cp.async — NO tcgen05)
// ===========================================================================
__device__ __forceinline__ uint32_t smem_u32(const void* p) {
    uint32_t a;
    asm("{ .reg .u64 t; cvta.to.shared.u64 t, %1; cvt.u32.u64 %0, t; }"
        : "=r"(a) : "l"(p));
    return a;
}
__device__ __forceinline__ uint32_t pkbf(__nv_bfloat16 a, __nv_bfloat16 b) {
    __nv_bfloat162 t(a, b);                 // a -> low half (lower address)
    return *reinterpret_cast<uint32_t*>(&t);
}
__device__ __forceinline__ void bsplit(float x, __nv_bfloat16& h, __nv_bfloat16& l) {
    h = __float2bfloat16(x);
    l = __float2bfloat16(x - __bfloat162float(h));
}
__device__ __forceinline__ void ldsm4(uint32_t* v, uint32_t addr) {
    asm volatile("ldmatrix.sync.aligned.m8n8.x4.shared.b16 {%0,%1,%2,%3}, [%4];"
                 : "=r"(v[0]), "=r"(v[1]), "=r"(v[2]), "=r"(v[3]) : "r"(addr));
}
__device__ __forceinline__ void mma_bf16(float* d, const uint32_t* a, const uint32_t* b) {
    asm volatile(
        "mma.sync.aligned.m16n8k16.row.col.f32.bf16.bf16.f32 "
        "{%0,%1,%2,%3}, {%4,%5,%6,%7}, {%8,%9}, {%0,%1,%2,%3};"
        : "+f"(d[0]), "+f"(d[1]), "+f"(d[2]), "+f"(d[3])
        : "r"(a[0]), "r"(a[1]), "r"(a[2]), "r"(a[3]), "r"(b[0]), "r"(b[1]));
}
__device__ __forceinline__ void cpasync16(uint32_t dst, const void* src) {
    asm volatile("cp.async.cg.shared.global [%0], [%1], 16;"
                 :: "r"(dst), "l"(src) : "memory");
}
__device__ __forceinline__ void cp_commit() {
    asm volatile("cp.async.commit_group;" ::: "memory");
}
__device__ __forceinline__ void cp_wait0() {
    asm volatile("cp.async.wait_group 0;" ::: "memory");
}

// ---- f32x2 packed-math helpers (stage 1) ----
__device__ __forceinline__ unsigned long long f32x2_dup(float a) {
    unsigned long long r;
    asm("mov.b64 %0, {%1, %1};" : "=l"(r) : "f"(a));
    return r;
}
__device__ __forceinline__ unsigned long long f32x2_fma(unsigned long long a,
                                                        unsigned long long b,
                                                        unsigned long long c) {
    unsigned long long d;
    asm("fma.rn.f32x2 %0, %1, %2, %3;" : "=l"(d) : "l"(a), "l"(b), "l"(c));
    return d;
}
__device__ __forceinline__ void f32x2_unpack(unsigned long long v, float& lo, float& hi) {
    asm("mov.b64 {%0, %1}, %2;" : "=f"(lo), "=f"(hi) : "l"(v));
}

// ===========================================================================
// Stage 1: fp32 SGEMM (K=256) — proven baseline kernel, 33 µs
// ===========================================================================
__global__ __launch_bounds__(256)
void gwnn_sgemm128_s1(const float* __restrict__ A,
                      const float* __restrict__ B,
                      float* __restrict__ C,
                      int K)
{
    constexpr int BM = 64, BN = 128, BK = 16, TM = 4, TN = 8;
    __shared__ float As[BK][BM];
    __shared__ float Bs[BK][BN];

    const int tid  = threadIdx.x;
    const int trow = tid >> 4;
    const int tcol = tid & 15;
    const int blockM = blockIdx.x * BM;

    const int aRow = tid >> 2;
    const int aCol = (tid & 3) << 2;
    const float* Aptr = A + (size_t)(blockM + aRow) * K + aCol;

    unsigned long long acc[TM][TN / 2];
    #pragma unroll
    for (int i = 0; i < TM; i++)
        #pragma unroll
        for (int j = 0; j < TN / 2; j++) acc[i][j] = 0ULL;

    for (int k0 = 0; k0 < K; k0 += BK) {
        float4 av = *reinterpret_cast<const float4*>(Aptr + k0);
        As[aCol + 0][aRow] = av.x;
        As[aCol + 1][aRow] = av.y;
        As[aCol + 2][aRow] = av.z;
        As[aCol + 3][aRow] = av.w;
        #pragma unroll
        for (int i = 0; i < 2; i++) {
            int off  = tid * 4 + i * 1024;
            int bRow = off >> 7;
            int bCol = off & 127;
            *reinterpret_cast<float4*>(&Bs[bRow][bCol]) =
                *reinterpret_cast<const float4*>(B + (size_t)(k0 + bRow) * BN + bCol);
        }
        __syncthreads();
        #pragma unroll
        for (int kk = 0; kk < BK; kk++) {
            float4 af = *reinterpret_cast<const float4*>(&As[kk][trow * TM]);
            ulonglong2 bq0 = *reinterpret_cast<const ulonglong2*>(&Bs[kk][tcol * TN]);
            ulonglong2 bq1 = *reinterpret_cast<const ulonglong2*>(&Bs[kk][tcol * TN + 4]);
            unsigned long long bp[4] = { bq0.x, bq0.y, bq1.x, bq1.y };
            float a_[4] = { af.x, af.y, af.z, af.w };
            #pragma unroll
            for (int i = 0; i < TM; i++) {
                unsigned long long ad = f32x2_dup(a_[i]);
                #pragma unroll
                for (int j = 0; j < TN / 2; j++)
                    acc[i][j] = f32x2_fma(ad, bp[j], acc[i][j]);
            }
        }
        __syncthreads();
    }
    #pragma unroll
    for (int i = 0; i < TM; i++) {
        const int row = blockM + trow * TM + i;
        float c[TN];
        #pragma unroll
        for (int j = 0; j < TN / 2; j++) {
            float lo, hi;
            f32x2_unpack(acc[i][j], lo, hi);
            c[2 * j] = lo; c[2 * j + 1] = hi;
        }
        float* Crow = C + (size_t)row * BN + tcol * TN;
        *reinterpret_cast<float4*>(Crow)     = make_float4(c[0], c[1], c[2], c[3]);
        *reinterpret_cast<float4*>(Crow + 4) = make_float4(c[4], c[5], c[6], c[7]);
    }
}

// ===========================================================================
// Convert T[8192][128] fp32 -> Bhi/Blo [128][8192] bf16 (transposed, K-major)
// ===========================================================================
__global__ __launch_bounds__(256)
void gwnn_convertB(const float* __restrict__ T,
                   __nv_bfloat16* __restrict__ Bhi,
                   __nv_bfloat16* __restrict__ Blo)
{
    __shared__ float s[64][129];
    const int tid = threadIdx.x;
    const int k0  = blockIdx.x * 64;

    #pragma unroll
    for (int i = 0; i < 8; i++) {
        int e   = tid + i * 256;
        int row = e >> 5;
        int c4  = e & 31;
        float4 v = *reinterpret_cast<const float4*>(T + (size_t)(k0 + row) * 128 + c4 * 4);
        s[row][c4 * 4 + 0] = v.x;
        s[row][c4 * 4 + 1] = v.y;
        s[row][c4 * 4 + 2] = v.z;
        s[row][c4 * 4 + 3] = v.w;
    }
    __syncthreads();

    const int w = tid >> 5, l = tid & 31;
    #pragma unroll
    for (int cc = 0; cc < 16; cc++) {
        int c = w + cc * 8;
        #pragma unroll
        for (int kk = l; kk < 64; kk += 32) {
            float v = s[kk][c];
            __nv_bfloat16 h, lo;
            bsplit(v, h, lo);
            Bhi[(size_t)c * NN + k0 + kk] = h;
            Blo[(size_t)c * NN + k0 + kk] = lo;
        }
    }
}

// ===========================================================================
// HMMA stage: D[64tile,128] = A[NN,NN](fp32, split on the fly) @ (Bhi+Blo)^T
// 3-term bf16 split via mma.sync.m16n8k16 (base sm_103 target — no tcgen05).
// CTA: 256 thr = 8 warps; CTA tile 64(M)x128(N); warp tile 32x32; K-chunk 64.
// MODE 0: write fp32 row-major. MODE 1: scale by rowScale, write bf16 hi/lo
// transposed (becomes next stage's B).
// ===========================================================================
static constexpr int KC = 64;              // k per chunk (rows of 128B in SMEM)
static constexpr int NC = NN / KC;         // 128 chunks
static constexpr int AH_OFF = 0;           // A hi: 64 rows x 128B = 8 KB
static constexpr int AL_OFF = 8192;
static constexpr int BH_OFF = 16384;       // B hi: 128 rows x 128B = 16 KB
static constexpr int BL_OFF = 32768;
static constexpr int BUFB   = 49152;       // one buffer
static constexpr int SMEMB  = 2 * BUFB;    // 96 KB double-buffered

__device__ __forceinline__ void loadA_regs(float4* av, const float* __restrict__ Ap,
                                           int k0, int tid) {
    #pragma unroll
    for (int i = 0; i < 4; i++) {
        int e = tid + i * 256;           // 64 rows x 16 float4
        int row = e >> 4, c4 = e & 15;
        av[i] = *reinterpret_cast<const float4*>(Ap + (size_t)row * NN + k0 + c4 * 4);
    }
}
__device__ __forceinline__ void storeA_split(char* smemBuf, const float4* av, int tid) {
    #pragma unroll
    for (int i = 0; i < 4; i++) {
        int e = tid + i * 256;
        int row = e >> 4, c4 = e & 15;
        __nv_bfloat16 h0, h1, h2, h3, l0, l1, l2, l3;
        bsplit(av[i].x, h0, l0); bsplit(av[i].y, h1, l1);
        bsplit(av[i].z, h2, l2); bsplit(av[i].w, h3, l3);
        uint32_t off = (uint32_t)(row * 128) + (((uint32_t)(c4 * 8)) ^ ((uint32_t)(row & 7) << 4));
        uint2 hw; hw.x = pkbf(h0, h1); hw.y = pkbf(h2, h3);
        uint2 lw; lw.x = pkbf(l0, l1); lw.y = pkbf(l2, l3);
        *reinterpret_cast<uint2*>(smemBuf + AH_OFF + off) = hw;
        *reinterpret_cast<uint2*>(smemBuf + AL_OFF + off) = lw;
    }
}
__device__ __forceinline__ void issueB_cpasync(uint32_t sbBuf,
                                               const __nv_bfloat16* __restrict__ Bhi,
                                               const __nv_bfloat16* __restrict__ Blo,
                                               int k0, int tid) {
    #pragma unroll
    for (int i = 0; i < 8; i++) {
        int half = i >> 2;                       // 0: hi, 1: lo
        int e = tid + (i & 3) * 256;             // 128 rows x 8 float4
        int row = e >> 3, f4 = e & 7;
        uint32_t off = (uint32_t)(row * 128) + (((uint32_t)(f4 * 16)) ^ ((uint32_t)(row & 7) << 4));
        const __nv_bfloat16* src = (half ? Blo : Bhi) + (size_t)row * NN + k0 + f4 * 8;
        cpasync16(sbBuf + (half ? BL_OFF : BH_OFF) + off, src);
    }
}

template<int MODE>
__global__ __launch_bounds__(256, 1)
void gwnn_hmma_stage(const float* __restrict__ A,
                     const __nv_bfloat16* __restrict__ Bhi,
                     const __nv_bfloat16* __restrict__ Blo,
                     const float* __restrict__ rowScale,
                     float* __restrict__ outF,
                     __nv_bfloat16* __restrict__ outHi,
                     __nv_bfloat16* __restrict__ outLo)
{
    extern __shared__ char smem[];
    const uint32_t sb = smem_u32(smem);
    const int tid = threadIdx.x;
    const int wid = tid >> 5, lid = tid & 31;
    const int wm = wid >> 2;                 // 0..1 -> M offset wm*32
    const int wn = wid & 3;                  // 0..3 -> N offset wn*32
    const int blockM = blockIdx.x * 64;
    const float* Ap = A + (size_t)blockM * NN;

    // Per-lane ldmatrix address constants (swizzle folded in):
    // sw128(row*128 + col) == row*128 + (col ^ ((row&7)<<4)) for col < 128.
    const int mat = lid >> 3, r = lid & 7;
    const uint32_t xorv  = (uint32_t)r << 4;
    const uint32_t aRowB = (uint32_t)((wm * 32 + (mat & 1) * 8 + r) * 128);
    const uint32_t aColB = (uint32_t)((mat >> 1) * 16);
    const uint32_t bRowB = (uint32_t)((wn * 32 + (mat >> 1) * 8 + r) * 128);
    const uint32_t bColB = (uint32_t)((mat & 1) * 16);

    float d[2][4][4] = {};
    float4 av[4];

    // ---- prologue: chunk 0 -> buffer 0
    loadA_regs(av, Ap, 0, tid);
    issueB_cpasync(sb, Bhi, Blo, 0, tid);
    cp_commit();
    storeA_split(smem, av, tid);
    cp_wait0();
    __syncthreads();

    // ---- mainloop
    for (int c = 0; c < NC; c++) {
        const int buf = c & 1;
        const uint32_t bufoff = (uint32_t)buf * BUFB;
        const bool more = (c + 1) < NC;

        if (more) {
            loadA_regs(av, Ap, (c + 1) * KC, tid);
            issueB_cpasync(sb + (bufoff ^ BUFB), Bhi, Blo, (c + 1) * KC, tid);
            cp_commit();
        }

        // compute on current buffer: 4 k16 steps
        const uint32_t baseA = sb + bufoff + AH_OFF;
        const uint32_t baseB = sb + bufoff + BH_OFF;
        #pragma unroll
        for (int i16 = 0; i16 < 4; i16++) {
            const uint32_t kb = (uint32_t)i16 * 32;
            uint32_t ah[2][4], al[2][4], bh[2][4], bl[2][4];
            #pragma unroll
            for (int mi = 0; mi < 2; mi++) {
                uint32_t addr = baseA + aRowB + (uint32_t)mi * 2048 + ((kb + aColB) ^ xorv);
                ldsm4(ah[mi], addr);
                ldsm4(al[mi], addr + (AL_OFF - AH_OFF));
            }
            #pragma unroll
            for (int ni = 0; ni < 2; ni++) {
                uint32_t addr = baseB + bRowB + (uint32_t)ni * 2048 + ((kb + bColB) ^ xorv);
                ldsm4(bh[ni], addr);
                ldsm4(bl[ni], addr + (BL_OFF - BH_OFF));
            }
            #pragma unroll
            for (int mi = 0; mi < 2; mi++)
                #pragma unroll
                for (int ni = 0; ni < 2; ni++)
                    #pragma unroll
                    for (int h = 0; h < 2; h++) {
                        const int j = ni * 2 + h;
                        mma_bf16(d[mi][j], ah[mi], &bh[ni][h * 2]);
                        mma_bf16(d[mi][j], ah[mi], &bl[ni][h * 2]);
                        mma_bf16(d[mi][j], al[mi], &bh[ni][h * 2]);
                    }
        }

        if (more) {
            storeA_split(smem + (bufoff ^ BUFB), av, tid);
            cp_wait0();
        }
        __syncthreads();
    }

    // ---- epilogue
    const int gRow0 = blockM + wm * 32 + (lid >> 2);
    const int col0  = wn * 32 + 2 * (lid & 3);
    #pragma unroll
    for (int mi = 0; mi < 2; mi++) {
        #pragma unroll
        for (int h = 0; h < 2; h++) {
            const int row = gRow0 + mi * 16 + h * 8;
            if (MODE == 0) {
                float* dst = outF + (size_t)row * 128 + col0;
                #pragma unroll
                for (int j = 0; j < 4; j++) {
                    float2 v = make_float2(d[mi][j][h * 2], d[mi][j][h * 2 + 1]);
                    *reinterpret_cast<float2*>(dst + j * 8) = v;
                }
            } else {
                const float s = rowScale[row];
                #pragma unroll
                for (int j = 0; j < 4; j++) {
                    #pragma unroll
                    for (int e = 0; e < 2; e++) {
                        const int cidx = col0 + j * 8 + e;
                        float v = d[mi][j][h * 2 + e] * s;
                        __nv_bfloat16 hh, ll;
                        bsplit(v, hh, ll);
                        outHi[(size_t)cidx * NN + row] = hh;
                        outLo[(size_t)cidx * NN + row] = ll;
                    }
                }
            }
        }
    }
}

// ===========================================================================
// Launch
// ===========================================================================
extern "C" void kernel_launch(void* const* d_in, const int* in_sizes, int n_in,
                              void* d_out, int out_size)
{
    const float* features     = (const float*)d_in[0];   // [8192, 256]
    const float* wavelets     = (const float*)d_in[1];   // [8192, 8192]
    const float* wavelets_inv = (const float*)d_in[2];   // [8192, 8192]
    const float* weight       = (const float*)d_in[3];   // [256, 128]
    const float* filt         = (const float*)d_in[4];   // [8192]
    float* out = (float*)d_out;                          // [8192, 128]

    float* T; __nv_bfloat16 *Bhi, *Blo, *Shi, *Slo;
    cudaGetSymbolAddress((void**)&T,   g_T);
    cudaGetSymbolAddress((void**)&Bhi, g_Bhi);
    cudaGetSymbolAddress((void**)&Blo, g_Blo);
    cudaGetSymbolAddress((void**)&Shi, g_Shi);
    cudaGetSymbolAddress((void**)&Slo, g_Slo);

    cudaFuncSetAttribute(gwnn_hmma_stage<0>,
                         cudaFuncAttributeMaxDynamicSharedMemorySize, SMEMB);
    cudaFuncSetAttribute(gwnn_hmma_stage<1>,
                         cudaFuncAttributeMaxDynamicSharedMemorySize, SMEMB);

    // Stage 1: T = features @ W (fp32, K=256)
    gwnn_sgemm128_s1<<<NN / 64, 256>>>(features, weight, T, CIN);
    // Convert T -> transposed bf16 hi/lo (stage-2 B operand)
    gwnn_convertB<<<NN / 64, 256>>>(T, Bhi, Blo);
    // Stage 2: S = filt ⊙ (Wi @ T); epilogue emits stage-3's B directly
    gwnn_hmma_stage<1><<<NN / 64, 256, SMEMB>>>(
        wavelets_inv, Bhi, Blo, filt, nullptr, Shi, Slo);
    // Stage 3: out = Wv @ S
    gwnn_hmma_stage<0><<<NN / 64, 256, SMEMB>>>(
        wavelets, Shi, Slo, nullptr, out, nullptr, nullptr);
}